// round 4
// baseline (speedup 1.0000x reference)
#include <cuda_runtime.h>

#define NN 50000
#define EE 800000
#define ET 850000        // EE + NN self loops
#define FIN 128
#define D1 256           // H1*C1 = 4*64
#define C1C 64
#define NH1 4
#define D2 128
#define NG 32
#define NCLS 5
#define NEG_SLOPE 0.2f

// ---------------- scratch (static device globals; no runtime alloc) --------
__device__ float    g_h1[(size_t)NN * D1];      // layer1 transformed features
__device__ float    g_out1[(size_t)NN * D1];    // layer1 aggregated output (elu'd in place)
__device__ float    g_h2[(size_t)NN * D2];      // layer2 transformed features
__device__ float    g_out2[(size_t)NN * D2];    // layer2 aggregated output (elu'd in place)
__device__ float    g_asrc1[NN * NH1], g_adst1[NN * NH1];
__device__ unsigned g_amax1[NN * NH1];
__device__ float    g_den1[NN * NH1];
__device__ float    g_alpha1[(size_t)ET * NH1];
__device__ float    g_asrc2[NN], g_adst2[NN];
__device__ unsigned g_amax2[NN];
__device__ float    g_den2[NN];
__device__ float    g_alpha2[ET];
__device__ float    g_pool[NG * D2];
__device__ float    g_cnt[NG];

// ordered-uint encoding for float atomicMax
__device__ __forceinline__ unsigned fenc(float f) {
    unsigned b = __float_as_uint(f);
    return (b & 0x80000000u) ? ~b : (b | 0x80000000u);
}
__device__ __forceinline__ float fdec(unsigned e) {
    unsigned b = (e & 0x80000000u) ? (e & 0x7fffffffu) : ~e;
    return __uint_as_float(b);
}

// edge_index is int32 (JAX x64 disabled -> int64 request silently becomes int32)
__device__ __forceinline__ void edge_sd(const int* __restrict__ ei, int e, int& s, int& d) {
    if (e < EE) { s = ei[e]; d = ei[EE + e]; }
    else        { s = e - EE; d = s; }
}

// ---------------- init ------------------------------------------------------
__global__ void init_kernel() {
    int i0 = blockIdx.x * blockDim.x + threadIdx.x;
    int stride = gridDim.x * blockDim.x;
    for (int i = i0; i < NN * D1; i += stride) g_out1[i] = 0.f;
    for (int i = i0; i < NN * D2; i += stride) g_out2[i] = 0.f;
    for (int i = i0; i < NN * NH1; i += stride) { g_den1[i] = 0.f; g_amax1[i] = 0u; }
    for (int i = i0; i < NN; i += stride)       { g_den2[i] = 0.f; g_amax2[i] = 0u; }
    for (int i = i0; i < NG * D2; i += stride) g_pool[i] = 0.f;
    if (i0 < NG) g_cnt[i0] = 0.f;
}

// ---------------- GEMM: H[r, tid] = sum_k X[r,k] * W[k, tid] ---------------
template <int KDIM, int NDIM, int TM>
__global__ void gemm_k(const float* __restrict__ X, const float* __restrict__ W,
                       float* __restrict__ H) {
    __shared__ __align__(16) float xs[TM * KDIM];
    int row0 = blockIdx.x * TM;
    int tid = threadIdx.x;   // NDIM threads
    for (int i = tid; i < TM * KDIM; i += NDIM) {
        int m = i / KDIM, k = i - m * KDIM;
        int r = row0 + m;
        xs[i] = (r < NN) ? X[(size_t)r * KDIM + k] : 0.f;
    }
    __syncthreads();
    float acc[TM];
#pragma unroll
    for (int m = 0; m < TM; m++) acc[m] = 0.f;
    for (int k = 0; k < KDIM; k += 4) {
        float w0 = W[(size_t)(k + 0) * NDIM + tid];
        float w1 = W[(size_t)(k + 1) * NDIM + tid];
        float w2 = W[(size_t)(k + 2) * NDIM + tid];
        float w3 = W[(size_t)(k + 3) * NDIM + tid];
#pragma unroll
        for (int m = 0; m < TM; m++) {
            float4 xv = *reinterpret_cast<const float4*>(&xs[m * KDIM + k]);
            acc[m] = fmaf(xv.x, w0, acc[m]);
            acc[m] = fmaf(xv.y, w1, acc[m]);
            acc[m] = fmaf(xv.z, w2, acc[m]);
            acc[m] = fmaf(xv.w, w3, acc[m]);
        }
    }
#pragma unroll
    for (int m = 0; m < TM; m++) {
        int r = row0 + m;
        if (r < NN) H[(size_t)r * NDIM + tid] = acc[m];
    }
}

// ---------------- attention scores -----------------------------------------
// one warp per (node, head) : a_src/a_dst = dot(h[n,h,:], att_*[h,:])
__global__ void ascore1_k(const float* __restrict__ att_s, const float* __restrict__ att_d) {
    int g = blockIdx.x * blockDim.x + threadIdx.x;
    int warp = g >> 5, lane = g & 31;
    if (warp >= NN * NH1) return;
    int n = warp >> 2, h = warp & 3;
    const float* hp = &g_h1[(size_t)n * D1 + h * C1C];
    float s = 0.f, d0 = 0.f;
#pragma unroll
    for (int c = lane; c < C1C; c += 32) {
        float v = hp[c];
        s  = fmaf(v, __ldg(&att_s[h * C1C + c]), s);
        d0 = fmaf(v, __ldg(&att_d[h * C1C + c]), d0);
    }
#pragma unroll
    for (int o = 16; o; o >>= 1) {
        s  += __shfl_down_sync(0xffffffffu, s, o);
        d0 += __shfl_down_sync(0xffffffffu, d0, o);
    }
    if (!lane) { g_asrc1[warp] = s; g_adst1[warp] = d0; }
}

// one warp per node for layer 2 (1 head, 128 channels)
__global__ void ascore2_k(const float* __restrict__ att_s, const float* __restrict__ att_d) {
    int g = blockIdx.x * blockDim.x + threadIdx.x;
    int warp = g >> 5, lane = g & 31;
    if (warp >= NN) return;
    const float* hp = &g_h2[(size_t)warp * D2];
    float s = 0.f, d0 = 0.f;
#pragma unroll
    for (int c = lane; c < D2; c += 32) {
        float v = hp[c];
        s  = fmaf(v, __ldg(&att_s[c]), s);
        d0 = fmaf(v, __ldg(&att_d[c]), d0);
    }
#pragma unroll
    for (int o = 16; o; o >>= 1) {
        s  += __shfl_down_sync(0xffffffffu, s, o);
        d0 += __shfl_down_sync(0xffffffffu, d0, o);
    }
    if (!lane) { g_asrc2[warp] = s; g_adst2[warp] = d0; }
}

// ---------------- edge pass A: leaky-relu + segment max ---------------------
__global__ void edgeA1_k(const int* __restrict__ ei) {
    int e = blockIdx.x * blockDim.x + threadIdx.x;
    if (e >= ET) return;
    int s, d; edge_sd(ei, e, s, d);
#pragma unroll
    for (int h = 0; h < NH1; h++) {
        float a = g_asrc1[s * NH1 + h] + g_adst1[d * NH1 + h];
        a = (a > 0.f) ? a : NEG_SLOPE * a;
        g_alpha1[(size_t)e * NH1 + h] = a;
        atomicMax(&g_amax1[d * NH1 + h], fenc(a));
    }
}
__global__ void edgeA2_k(const int* __restrict__ ei) {
    int e = blockIdx.x * blockDim.x + threadIdx.x;
    if (e >= ET) return;
    int s, d; edge_sd(ei, e, s, d);
    float a = g_asrc2[s] + g_adst2[d];
    a = (a > 0.f) ? a : NEG_SLOPE * a;
    g_alpha2[e] = a;
    atomicMax(&g_amax2[d], fenc(a));
}

// ---------------- edge pass B: exp + segment sum ----------------------------
__global__ void edgeB1_k(const int* __restrict__ ei) {
    int e = blockIdx.x * blockDim.x + threadIdx.x;
    if (e >= ET) return;
    int s, d; edge_sd(ei, e, s, d);
#pragma unroll
    for (int h = 0; h < NH1; h++) {
        float m = fdec(g_amax1[d * NH1 + h]);
        float ex = __expf(g_alpha1[(size_t)e * NH1 + h] - m);
        g_alpha1[(size_t)e * NH1 + h] = ex;
        atomicAdd(&g_den1[d * NH1 + h], ex);
    }
}
__global__ void edgeB2_k(const int* __restrict__ ei) {
    int e = blockIdx.x * blockDim.x + threadIdx.x;
    if (e >= ET) return;
    int s, d; edge_sd(ei, e, s, d);
    float m = fdec(g_amax2[d]);
    float ex = __expf(g_alpha2[e] - m);
    g_alpha2[e] = ex;
    atomicAdd(&g_den2[d], ex);
}

// ---------------- edge pass C: weighted scatter-add of features ------------
// one warp per edge; layer1: 256 floats (2 x float4 per lane)
__global__ void edgeC1_k(const int* __restrict__ ei) {
    int g = blockIdx.x * blockDim.x + threadIdx.x;
    int e = g >> 5, lane = g & 31;
    if (e >= ET) return;
    int s, d; edge_sd(ei, e, s, d);
    float wsel = 0.f;
    if (lane < NH1) {
        float ex = g_alpha1[(size_t)e * NH1 + lane];
        float den = g_den1[d * NH1 + lane];
        wsel = ex / (den + 1e-16f);
    }
    const float4* hs = reinterpret_cast<const float4*>(g_h1 + (size_t)s * D1);
    float* od = g_out1 + (size_t)d * D1;
#pragma unroll
    for (int it = 0; it < 2; it++) {
        int q = lane + 32 * it;      // float4 index 0..63
        float4 v = hs[q];
        int c = q * 4;
        float w = __shfl_sync(0xffffffffu, wsel, c >> 6);
        atomicAdd(od + c + 0, v.x * w);
        atomicAdd(od + c + 1, v.y * w);
        atomicAdd(od + c + 2, v.z * w);
        atomicAdd(od + c + 3, v.w * w);
    }
}
// layer2: 128 floats (1 x float4 per lane), single head
__global__ void edgeC2_k(const int* __restrict__ ei) {
    int g = blockIdx.x * blockDim.x + threadIdx.x;
    int e = g >> 5, lane = g & 31;
    if (e >= ET) return;
    int s, d; edge_sd(ei, e, s, d);
    float w = g_alpha2[e] / (g_den2[d] + 1e-16f);
    const float4* hs = reinterpret_cast<const float4*>(g_h2 + (size_t)s * D2);
    float* od = g_out2 + (size_t)d * D2;
    float4 v = hs[lane];
    int c = lane * 4;
    atomicAdd(od + c + 0, v.x * w);
    atomicAdd(od + c + 1, v.y * w);
    atomicAdd(od + c + 2, v.z * w);
    atomicAdd(od + c + 3, v.w * w);
}

// ---------------- ELU (+bias) in place --------------------------------------
__global__ void elu_k(float* __restrict__ p, const float* __restrict__ bias, int dim, int total) {
    int i = blockIdx.x * blockDim.x + threadIdx.x;
    if (i >= total) return;
    float v = p[i] + __ldg(&bias[i % dim]);
    p[i] = (v > 0.f) ? v : expm1f(v);
}

// ---------------- pooling ---------------------------------------------------
__global__ void count_k(const int* __restrict__ batch) {
    int n = blockIdx.x * blockDim.x + threadIdx.x;
    if (n >= NN) return;
    atomicAdd(&g_cnt[batch[n]], 1.f);
}
__global__ void pool_k(const int* __restrict__ batch) {
    int i = blockIdx.x * blockDim.x + threadIdx.x;
    if (i >= NN * D2) return;
    int n = i >> 7, c = i & 127;
    atomicAdd(&g_pool[batch[n] * D2 + c], g_out2[i]);
}
__global__ void final_k(const float* __restrict__ lin_w, const float* __restrict__ lin_b,
                        float* __restrict__ out) {
    int t = threadIdx.x;
    if (t >= NG * NCLS) return;
    int gph = t / NCLS, k = t - gph * NCLS;
    float inv = 1.f / fmaxf(g_cnt[gph], 1.f);
    float acc = 0.f;
    for (int c = 0; c < D2; c++)
        acc = fmaf(g_pool[gph * D2 + c] * inv, __ldg(&lin_w[c * NCLS + k]), acc);
    out[t] = acc + lin_b[k];
}

// ---------------- driver -----------------------------------------------------
extern "C" void kernel_launch(void* const* d_in, const int* in_sizes, int n_in,
                              void* d_out, int out_size) {
    const float* x        = (const float*)d_in[0];
    const int*   ei       = (const int*)d_in[1];
    const int*   batch    = (const int*)d_in[2];
    const float* W1       = (const float*)d_in[3];
    const float* att_src1 = (const float*)d_in[4];
    const float* att_dst1 = (const float*)d_in[5];
    const float* b1       = (const float*)d_in[6];
    const float* W2       = (const float*)d_in[7];
    const float* att_src2 = (const float*)d_in[8];
    const float* att_dst2 = (const float*)d_in[9];
    const float* b2       = (const float*)d_in[10];
    const float* lin_w    = (const float*)d_in[11];
    const float* lin_b    = (const float*)d_in[12];
    float* out = (float*)d_out;

    float* h1p;   cudaGetSymbolAddress((void**)&h1p, g_h1);
    float* out1p; cudaGetSymbolAddress((void**)&out1p, g_out1);
    float* h2p;   cudaGetSymbolAddress((void**)&h2p, g_h2);
    float* out2p; cudaGetSymbolAddress((void**)&out2p, g_out2);

    init_kernel<<<1184, 256>>>();

    // ---- layer 1 ----
    gemm_k<FIN, D1, 32><<<(NN + 31) / 32, D1>>>(x, W1, h1p);
    ascore1_k<<<(NN * NH1 * 32 + 255) / 256, 256>>>(att_src1, att_dst1);
    edgeA1_k<<<(ET + 255) / 256, 256>>>(ei);
    edgeB1_k<<<(ET + 255) / 256, 256>>>(ei);
    edgeC1_k<<<(ET * 32 + 255) / 256, 256>>>(ei);
    elu_k<<<(NN * D1 + 255) / 256, 256>>>(out1p, b1, D1, NN * D1);

    // ---- layer 2 ----
    gemm_k<D1, D2, 32><<<(NN + 31) / 32, D2>>>(out1p, W2, h2p);
    ascore2_k<<<(NN * 32 + 255) / 256, 256>>>(att_src2, att_dst2);
    edgeA2_k<<<(ET + 255) / 256, 256>>>(ei);
    edgeB2_k<<<(ET + 255) / 256, 256>>>(ei);
    edgeC2_k<<<(ET * 32 + 255) / 256, 256>>>(ei);
    elu_k<<<(NN * D2 + 255) / 256, 256>>>(out2p, b2, D2, NN * D2);

    // ---- pooling + head ----
    count_k<<<(NN + 255) / 256, 256>>>(batch);
    pool_k<<<(NN * D2 + 255) / 256, 256>>>(batch);
    final_k<<<1, 256>>>(lin_w, lin_b, out);
}

// round 5
// speedup vs baseline: 2.0124x; 2.0124x over previous
#include <cuda_runtime.h>

#define NN 50000
#define EE 800000
#define ET 850000        // EE + NN self loops
#define FIN 128
#define D1 256           // H1*C1 = 4*64
#define C1C 64
#define NH1 4
#define D2 128
#define NG 32
#define NCLS 5
#define NEG_SLOPE 0.2f

// ---------------- scratch (static device globals) ---------------------------
__device__ float g_h1[(size_t)NN * D1];
__device__ float g_out1[(size_t)NN * D1];    // elu(bias+agg) of layer1
__device__ float g_h2[(size_t)NN * D2];
__device__ float g_out2[(size_t)NN * D2];    // elu(bias+agg) of layer2
__device__ float g_asrc1[NN * NH1], g_adst1[NN * NH1];
__device__ float g_invden1[NN * NH1];
__device__ float g_alpha1[(size_t)ET * NH1]; // CSR-ordered exp(alpha - max)
__device__ float g_asrc2[NN], g_adst2[NN];
__device__ float g_invden2[NN];
__device__ float g_alpha2[ET];
__device__ float g_pool[NG * D2];
__device__ float g_cnt[NG];
// CSR by destination
__device__ int g_deg[NN];
__device__ int g_rowptr[NN + 1];
__device__ int g_cursor[NN];
__device__ int g_col[ET];                    // src node of each CSR slot

__device__ __forceinline__ float lrelu(float a) { return (a > 0.f) ? a : NEG_SLOPE * a; }
__device__ __forceinline__ float elu(float v)   { return (v > 0.f) ? v : expm1f(v); }

// ---------------- init ------------------------------------------------------
__global__ void init_kernel() {
    int i0 = blockIdx.x * blockDim.x + threadIdx.x;
    int stride = gridDim.x * blockDim.x;
    for (int i = i0; i < NN; i += stride) g_deg[i] = 0;
    for (int i = i0; i < NG * D2; i += stride) g_pool[i] = 0.f;
    if (i0 < NG) g_cnt[i0] = 0.f;
}

// ---------------- CSR build -------------------------------------------------
__global__ void deg_k(const int* __restrict__ ei) {
    int e = blockIdx.x * blockDim.x + threadIdx.x;
    if (e >= ET) return;
    int d = (e < EE) ? ei[EE + e] : (e - EE);
    atomicAdd(&g_deg[d], 1);
}

// single-block exclusive scan over 50k degrees
__global__ void scan_k() {
    const int T = 1024;
    const int CH = (NN + T - 1) / T;   // 49
    __shared__ int part[T];
    int t = threadIdx.x;
    int base = t * CH;
    int s = 0;
    for (int i = 0; i < CH; i++) {
        int idx = base + i;
        if (idx < NN) s += g_deg[idx];
    }
    part[t] = s;
    __syncthreads();
    // inclusive Hillis scan
    for (int off = 1; off < T; off <<= 1) {
        int v = (t >= off) ? part[t - off] : 0;
        __syncthreads();
        part[t] += v;
        __syncthreads();
    }
    int run = part[t] - s;   // exclusive prefix of this chunk
    for (int i = 0; i < CH; i++) {
        int idx = base + i;
        if (idx < NN) {
            g_rowptr[idx] = run;
            g_cursor[idx] = run;
            run += g_deg[idx];
        }
    }
    if (t == 0) g_rowptr[NN] = ET;
}

__global__ void scatter_k(const int* __restrict__ ei) {
    int e = blockIdx.x * blockDim.x + threadIdx.x;
    if (e >= ET) return;
    int s, d;
    if (e < EE) { s = ei[e]; d = ei[EE + e]; }
    else        { s = e - EE; d = s; }
    int pos = atomicAdd(&g_cursor[d], 1);
    g_col[pos] = s;
}

// ---------------- GEMM: H[r, tid] = sum_k X[r,k] * W[k, tid] ---------------
template <int KDIM, int NDIM, int TM>
__global__ void gemm_k(const float* __restrict__ X, const float* __restrict__ W,
                       float* __restrict__ H) {
    __shared__ __align__(16) float xs[TM * KDIM];
    int row0 = blockIdx.x * TM;
    int tid = threadIdx.x;   // NDIM threads
    for (int i = tid; i < TM * KDIM; i += NDIM) {
        int m = i / KDIM, k = i - m * KDIM;
        int r = row0 + m;
        xs[i] = (r < NN) ? X[(size_t)r * KDIM + k] : 0.f;
    }
    __syncthreads();
    float acc[TM];
#pragma unroll
    for (int m = 0; m < TM; m++) acc[m] = 0.f;
    for (int k = 0; k < KDIM; k += 4) {
        float w0 = W[(size_t)(k + 0) * NDIM + tid];
        float w1 = W[(size_t)(k + 1) * NDIM + tid];
        float w2 = W[(size_t)(k + 2) * NDIM + tid];
        float w3 = W[(size_t)(k + 3) * NDIM + tid];
#pragma unroll
        for (int m = 0; m < TM; m++) {
            float4 xv = *reinterpret_cast<const float4*>(&xs[m * KDIM + k]);
            acc[m] = fmaf(xv.x, w0, acc[m]);
            acc[m] = fmaf(xv.y, w1, acc[m]);
            acc[m] = fmaf(xv.z, w2, acc[m]);
            acc[m] = fmaf(xv.w, w3, acc[m]);
        }
    }
#pragma unroll
    for (int m = 0; m < TM; m++) {
        int r = row0 + m;
        if (r < NN) H[(size_t)r * NDIM + tid] = acc[m];
    }
}

// ---------------- attention scores -----------------------------------------
__global__ void ascore1_k(const float* __restrict__ att_s, const float* __restrict__ att_d) {
    int g = blockIdx.x * blockDim.x + threadIdx.x;
    int warp = g >> 5, lane = g & 31;
    if (warp >= NN * NH1) return;
    int n = warp >> 2, h = warp & 3;
    const float* hp = &g_h1[(size_t)n * D1 + h * C1C];
    float s = 0.f, d0 = 0.f;
#pragma unroll
    for (int c = lane; c < C1C; c += 32) {
        float v = hp[c];
        s  = fmaf(v, __ldg(&att_s[h * C1C + c]), s);
        d0 = fmaf(v, __ldg(&att_d[h * C1C + c]), d0);
    }
#pragma unroll
    for (int o = 16; o; o >>= 1) {
        s  += __shfl_down_sync(0xffffffffu, s, o);
        d0 += __shfl_down_sync(0xffffffffu, d0, o);
    }
    if (!lane) { g_asrc1[warp] = s; g_adst1[warp] = d0; }
}

__global__ void ascore2_k(const float* __restrict__ att_s, const float* __restrict__ att_d) {
    int g = blockIdx.x * blockDim.x + threadIdx.x;
    int warp = g >> 5, lane = g & 31;
    if (warp >= NN) return;
    const float* hp = &g_h2[(size_t)warp * D2];
    float s = 0.f, d0 = 0.f;
#pragma unroll
    for (int c = lane; c < D2; c += 32) {
        float v = hp[c];
        s  = fmaf(v, __ldg(&att_s[c]), s);
        d0 = fmaf(v, __ldg(&att_d[c]), d0);
    }
#pragma unroll
    for (int o = 16; o; o >>= 1) {
        s  += __shfl_down_sync(0xffffffffu, s, o);
        d0 += __shfl_down_sync(0xffffffffu, d0, o);
    }
    if (!lane) { g_asrc2[warp] = s; g_adst2[warp] = d0; }
}

// ---------------- softmax over incoming edges (warp per dst node) ----------
// layer 1: 4 heads
__global__ void softmax1_k() {
    int g = blockIdx.x * blockDim.x + threadIdx.x;
    int d = g >> 5, lane = g & 31;
    if (d >= NN) return;
    int b = g_rowptr[d];
    int deg = g_rowptr[d + 1] - b;
    float ad0 = g_adst1[d * NH1 + 0], ad1 = g_adst1[d * NH1 + 1];
    float ad2 = g_adst1[d * NH1 + 2], ad3 = g_adst1[d * NH1 + 3];
    float mx0 = -1e30f, mx1 = -1e30f, mx2 = -1e30f, mx3 = -1e30f;
    for (int i = lane; i < deg; i += 32) {
        int s = g_col[b + i];
        const float* as = &g_asrc1[s * NH1];
        float a0 = lrelu(as[0] + ad0), a1 = lrelu(as[1] + ad1);
        float a2 = lrelu(as[2] + ad2), a3 = lrelu(as[3] + ad3);
        float* ap = &g_alpha1[(size_t)(b + i) * NH1];
        ap[0] = a0; ap[1] = a1; ap[2] = a2; ap[3] = a3;
        mx0 = fmaxf(mx0, a0); mx1 = fmaxf(mx1, a1);
        mx2 = fmaxf(mx2, a2); mx3 = fmaxf(mx3, a3);
    }
#pragma unroll
    for (int o = 16; o; o >>= 1) {
        mx0 = fmaxf(mx0, __shfl_xor_sync(0xffffffffu, mx0, o));
        mx1 = fmaxf(mx1, __shfl_xor_sync(0xffffffffu, mx1, o));
        mx2 = fmaxf(mx2, __shfl_xor_sync(0xffffffffu, mx2, o));
        mx3 = fmaxf(mx3, __shfl_xor_sync(0xffffffffu, mx3, o));
    }
    float dn0 = 0.f, dn1 = 0.f, dn2 = 0.f, dn3 = 0.f;
    for (int i = lane; i < deg; i += 32) {
        float* ap = &g_alpha1[(size_t)(b + i) * NH1];
        float e0 = __expf(ap[0] - mx0), e1 = __expf(ap[1] - mx1);
        float e2 = __expf(ap[2] - mx2), e3 = __expf(ap[3] - mx3);
        ap[0] = e0; ap[1] = e1; ap[2] = e2; ap[3] = e3;
        dn0 += e0; dn1 += e1; dn2 += e2; dn3 += e3;
    }
#pragma unroll
    for (int o = 16; o; o >>= 1) {
        dn0 += __shfl_xor_sync(0xffffffffu, dn0, o);
        dn1 += __shfl_xor_sync(0xffffffffu, dn1, o);
        dn2 += __shfl_xor_sync(0xffffffffu, dn2, o);
        dn3 += __shfl_xor_sync(0xffffffffu, dn3, o);
    }
    if (!lane) {
        g_invden1[d * NH1 + 0] = 1.f / (dn0 + 1e-16f);
        g_invden1[d * NH1 + 1] = 1.f / (dn1 + 1e-16f);
        g_invden1[d * NH1 + 2] = 1.f / (dn2 + 1e-16f);
        g_invden1[d * NH1 + 3] = 1.f / (dn3 + 1e-16f);
    }
}

// layer 2: 1 head
__global__ void softmax2_k() {
    int g = blockIdx.x * blockDim.x + threadIdx.x;
    int d = g >> 5, lane = g & 31;
    if (d >= NN) return;
    int b = g_rowptr[d];
    int deg = g_rowptr[d + 1] - b;
    float ad = g_adst2[d];
    float mx = -1e30f;
    for (int i = lane; i < deg; i += 32) {
        int s = g_col[b + i];
        float a = lrelu(g_asrc2[s] + ad);
        g_alpha2[b + i] = a;
        mx = fmaxf(mx, a);
    }
#pragma unroll
    for (int o = 16; o; o >>= 1) mx = fmaxf(mx, __shfl_xor_sync(0xffffffffu, mx, o));
    float dn = 0.f;
    for (int i = lane; i < deg; i += 32) {
        float e = __expf(g_alpha2[b + i] - mx);
        g_alpha2[b + i] = e;
        dn += e;
    }
#pragma unroll
    for (int o = 16; o; o >>= 1) dn += __shfl_xor_sync(0xffffffffu, dn, o);
    if (!lane) g_invden2[d] = 1.f / (dn + 1e-16f);
}

// ---------------- aggregation (warp per dst node, gather, no atomics) ------
// layer1: 256 channels, 2 float4 per lane; epilogue: *invden, +bias, elu
__global__ void agg1_k(const float* __restrict__ bias) {
    int g = blockIdx.x * blockDim.x + threadIdx.x;
    int d = g >> 5, lane = g & 31;
    if (d >= NN) return;
    int b = g_rowptr[d];
    int deg = g_rowptr[d + 1] - b;
    int h0 = lane >> 4;        // head for channels 4*lane ..
    float4 acc0 = {0.f, 0.f, 0.f, 0.f};
    float4 acc1 = {0.f, 0.f, 0.f, 0.f};
    for (int i = 0; i < deg; i++) {
        int s = g_col[b + i];
        const float* ap = &g_alpha1[(size_t)(b + i) * NH1];
        float a0 = ap[h0];           // head of first float4 (0 or 1)
        float a1 = ap[2 + h0];       // head of second float4 (2 or 3)
        const float4* hp = reinterpret_cast<const float4*>(g_h1 + (size_t)s * D1);
        float4 v0 = hp[lane];
        float4 v1 = hp[lane + 32];
        acc0.x = fmaf(v0.x, a0, acc0.x); acc0.y = fmaf(v0.y, a0, acc0.y);
        acc0.z = fmaf(v0.z, a0, acc0.z); acc0.w = fmaf(v0.w, a0, acc0.w);
        acc1.x = fmaf(v1.x, a1, acc1.x); acc1.y = fmaf(v1.y, a1, acc1.y);
        acc1.z = fmaf(v1.z, a1, acc1.z); acc1.w = fmaf(v1.w, a1, acc1.w);
    }
    float inv0 = g_invden1[d * NH1 + h0];
    float inv1 = g_invden1[d * NH1 + 2 + h0];
    const float4* bp = reinterpret_cast<const float4*>(bias);
    float4 b0 = __ldg(&bp[lane]);
    float4 b1 = __ldg(&bp[lane + 32]);
    float4 o0, o1;
    o0.x = elu(acc0.x * inv0 + b0.x); o0.y = elu(acc0.y * inv0 + b0.y);
    o0.z = elu(acc0.z * inv0 + b0.z); o0.w = elu(acc0.w * inv0 + b0.w);
    o1.x = elu(acc1.x * inv1 + b1.x); o1.y = elu(acc1.y * inv1 + b1.y);
    o1.z = elu(acc1.z * inv1 + b1.z); o1.w = elu(acc1.w * inv1 + b1.w);
    float4* op = reinterpret_cast<float4*>(g_out1 + (size_t)d * D1);
    op[lane] = o0;
    op[lane + 32] = o1;
}

// layer2: 128 channels, 1 float4 per lane, single head
__global__ void agg2_k(const float* __restrict__ bias) {
    int g = blockIdx.x * blockDim.x + threadIdx.x;
    int d = g >> 5, lane = g & 31;
    if (d >= NN) return;
    int b = g_rowptr[d];
    int deg = g_rowptr[d + 1] - b;
    float4 acc = {0.f, 0.f, 0.f, 0.f};
    for (int i = 0; i < deg; i++) {
        int s = g_col[b + i];
        float a = g_alpha2[b + i];
        const float4* hp = reinterpret_cast<const float4*>(g_h2 + (size_t)s * D2);
        float4 v = hp[lane];
        acc.x = fmaf(v.x, a, acc.x); acc.y = fmaf(v.y, a, acc.y);
        acc.z = fmaf(v.z, a, acc.z); acc.w = fmaf(v.w, a, acc.w);
    }
    float inv = g_invden2[d];
    const float4* bp = reinterpret_cast<const float4*>(bias);
    float4 bb = __ldg(&bp[lane]);
    float4 o;
    o.x = elu(acc.x * inv + bb.x); o.y = elu(acc.y * inv + bb.y);
    o.z = elu(acc.z * inv + bb.z); o.w = elu(acc.w * inv + bb.w);
    reinterpret_cast<float4*>(g_out2 + (size_t)d * D2)[lane] = o;
}

// ---------------- pooling + head --------------------------------------------
__global__ void count_k(const int* __restrict__ batch) {
    int n = blockIdx.x * blockDim.x + threadIdx.x;
    if (n >= NN) return;
    atomicAdd(&g_cnt[batch[n]], 1.f);
}
__global__ void pool_k(const int* __restrict__ batch) {
    int i = blockIdx.x * blockDim.x + threadIdx.x;
    if (i >= NN * D2) return;
    int n = i >> 7, c = i & 127;
    atomicAdd(&g_pool[batch[n] * D2 + c], g_out2[i]);
}
__global__ void final_k(const float* __restrict__ lin_w, const float* __restrict__ lin_b,
                        float* __restrict__ out) {
    int t = threadIdx.x;
    if (t >= NG * NCLS) return;
    int gph = t / NCLS, k = t - gph * NCLS;
    float inv = 1.f / fmaxf(g_cnt[gph], 1.f);
    float acc = 0.f;
    for (int c = 0; c < D2; c++)
        acc = fmaf(g_pool[gph * D2 + c] * inv, __ldg(&lin_w[c * NCLS + k]), acc);
    out[t] = acc + lin_b[k];
}

// ---------------- driver -----------------------------------------------------
extern "C" void kernel_launch(void* const* d_in, const int* in_sizes, int n_in,
                              void* d_out, int out_size) {
    const float* x        = (const float*)d_in[0];
    const int*   ei       = (const int*)d_in[1];
    const int*   batch    = (const int*)d_in[2];
    const float* W1       = (const float*)d_in[3];
    const float* att_src1 = (const float*)d_in[4];
    const float* att_dst1 = (const float*)d_in[5];
    const float* b1       = (const float*)d_in[6];
    const float* W2       = (const float*)d_in[7];
    const float* att_src2 = (const float*)d_in[8];
    const float* att_dst2 = (const float*)d_in[9];
    const float* b2       = (const float*)d_in[10];
    const float* lin_w    = (const float*)d_in[11];
    const float* lin_b    = (const float*)d_in[12];
    float* out = (float*)d_out;

    float* h1p;   cudaGetSymbolAddress((void**)&h1p, g_h1);
    float* out1p; cudaGetSymbolAddress((void**)&out1p, g_out1);
    float* h2p;   cudaGetSymbolAddress((void**)&h2p, g_h2);

    init_kernel<<<256, 256>>>();
    deg_k<<<(ET + 255) / 256, 256>>>(ei);
    scan_k<<<1, 1024>>>();
    scatter_k<<<(ET + 255) / 256, 256>>>(ei);

    // ---- layer 1 ----
    gemm_k<FIN, D1, 32><<<(NN + 31) / 32, D1>>>(x, W1, h1p);
    ascore1_k<<<(NN * NH1 * 32 + 255) / 256, 256>>>(att_src1, att_dst1);
    softmax1_k<<<(NN * 32 + 255) / 256, 256>>>();
    agg1_k<<<(NN * 32 + 255) / 256, 256>>>(b1);

    // ---- layer 2 ----
    gemm_k<D1, D2, 32><<<(NN + 31) / 32, D2>>>(out1p, W2, h2p);
    ascore2_k<<<(NN * 32 + 255) / 256, 256>>>(att_src2, att_dst2);
    softmax2_k<<<(NN * 32 + 255) / 256, 256>>>();
    agg2_k<<<(NN * 32 + 255) / 256, 256>>>(b2);

    // ---- pooling + head ----
    count_k<<<(NN + 255) / 256, 256>>>(batch);
    pool_k<<<(NN * D2 + 255) / 256, 256>>>(batch);
    final_k<<<1, 256>>>(lin_w, lin_b, out);
}

// round 6
// speedup vs baseline: 2.3298x; 1.1577x over previous
#include <cuda_runtime.h>

#define NN 50000
#define EE 800000
#define ET 850000        // EE + NN self loops
#define FIN 128
#define D1 256           // H1*C1 = 4*64
#define C1C 64
#define NH1 4
#define D2 128
#define NG 32
#define NCLS 5
#define NEG_SLOPE 0.2f

// ---------------- scratch (static device globals) ---------------------------
__device__ float g_h1[(size_t)NN * D1];
__device__ float g_out1[(size_t)NN * D1];
__device__ float g_h2[(size_t)NN * D2];
__device__ float g_out2[(size_t)NN * D2];
__device__ float g_asrc1[NN * NH1], g_adst1[NN * NH1];
__device__ float g_asrc2[NN], g_adst2[NN];
__device__ float g_pool[NG * D2];
__device__ float g_cnt[NG];
// CSR by destination
__device__ int g_deg[NN];
__device__ int g_rowptr[NN + 1];
__device__ int g_cursor[NN];
__device__ int g_col[ET];

__device__ __forceinline__ float lrelu(float a) { return (a > 0.f) ? a : NEG_SLOPE * a; }
__device__ __forceinline__ float elu(float v)   { return (v > 0.f) ? v : expm1f(v); }

// ---------------- init ------------------------------------------------------
__global__ void init_kernel() {
    int i0 = blockIdx.x * blockDim.x + threadIdx.x;
    int stride = gridDim.x * blockDim.x;
    for (int i = i0; i < NN; i += stride) g_deg[i] = 0;
    for (int i = i0; i < NG * D2; i += stride) g_pool[i] = 0.f;
    if (i0 < NG) g_cnt[i0] = 0.f;
}

// ---------------- CSR build -------------------------------------------------
__global__ void deg_k(const int* __restrict__ ei) {
    int e = blockIdx.x * blockDim.x + threadIdx.x;
    if (e >= ET) return;
    int d = (e < EE) ? ei[EE + e] : (e - EE);
    atomicAdd(&g_deg[d], 1);
}

__global__ void scan_k() {
    const int T = 1024;
    const int CH = (NN + T - 1) / T;
    __shared__ int part[T];
    int t = threadIdx.x;
    int base = t * CH;
    int s = 0;
    for (int i = 0; i < CH; i++) {
        int idx = base + i;
        if (idx < NN) s += g_deg[idx];
    }
    part[t] = s;
    __syncthreads();
    for (int off = 1; off < T; off <<= 1) {
        int v = (t >= off) ? part[t - off] : 0;
        __syncthreads();
        part[t] += v;
        __syncthreads();
    }
    int run = part[t] - s;
    for (int i = 0; i < CH; i++) {
        int idx = base + i;
        if (idx < NN) {
            g_rowptr[idx] = run;
            g_cursor[idx] = run;
            run += g_deg[idx];
        }
    }
    if (t == 0) g_rowptr[NN] = ET;
}

__global__ void scatter_k(const int* __restrict__ ei) {
    int e = blockIdx.x * blockDim.x + threadIdx.x;
    if (e >= ET) return;
    int s, d;
    if (e < EE) { s = ei[e]; d = ei[EE + e]; }
    else        { s = e - EE; d = s; }
    int pos = atomicAdd(&g_cursor[d], 1);
    g_col[pos] = s;
}

// ---------------- GEMM with packed f32x2 FMA --------------------------------
// H[r, tid] = sum_k X[r,k] * W[k, tid]
// x-tile stored k-major with padded stride so row-PAIRS load as 64-bit units.
template <int KDIM, int NDIM, int TM>
__global__ void gemm_k(const float* __restrict__ X, const float* __restrict__ W,
                       float* __restrict__ H) {
    constexpr int STRIDE = TM + 4;                  // 36 floats = 144B (16B-multiple)
    __shared__ __align__(16) float xs[KDIM * STRIDE];
    int row0 = blockIdx.x * TM;
    int tid = threadIdx.x;                          // NDIM threads
    for (int i = tid; i < TM * KDIM; i += NDIM) {
        int m = i / KDIM, k = i - m * KDIM;         // consecutive tid -> consecutive k (coalesced)
        int r = row0 + m;
        xs[k * STRIDE + m] = (r < NN) ? X[(size_t)r * KDIM + k] : 0.f;
    }
    __syncthreads();

    unsigned long long acc[TM / 2];
#pragma unroll
    for (int p = 0; p < TM / 2; p++) acc[p] = 0ull;

    for (int k = 0; k < KDIM; k += 2) {
        float wa = W[(size_t)k * NDIM + tid];
        float wb = W[(size_t)(k + 1) * NDIM + tid];
        unsigned long long wpa, wpb;
        asm("mov.b64 %0, {%1, %1};" : "=l"(wpa) : "f"(wa));
        asm("mov.b64 %0, {%1, %1};" : "=l"(wpb) : "f"(wb));
        const ulonglong2* xa = reinterpret_cast<const ulonglong2*>(&xs[k * STRIDE]);
        const ulonglong2* xb = reinterpret_cast<const ulonglong2*>(&xs[(k + 1) * STRIDE]);
#pragma unroll
        for (int q = 0; q < TM / 4; q++) {
            ulonglong2 va = xa[q];
            asm("fma.rn.f32x2 %0, %1, %2, %0;" : "+l"(acc[2 * q])     : "l"(va.x), "l"(wpa));
            asm("fma.rn.f32x2 %0, %1, %2, %0;" : "+l"(acc[2 * q + 1]) : "l"(va.y), "l"(wpa));
        }
#pragma unroll
        for (int q = 0; q < TM / 4; q++) {
            ulonglong2 vb = xb[q];
            asm("fma.rn.f32x2 %0, %1, %2, %0;" : "+l"(acc[2 * q])     : "l"(vb.x), "l"(wpb));
            asm("fma.rn.f32x2 %0, %1, %2, %0;" : "+l"(acc[2 * q + 1]) : "l"(vb.y), "l"(wpb));
        }
    }

#pragma unroll
    for (int p = 0; p < TM / 2; p++) {
        float lo, hi;
        asm("mov.b64 {%0, %1}, %2;" : "=f"(lo), "=f"(hi) : "l"(acc[p]));
        int r = row0 + 2 * p;
        if (r < NN)     H[(size_t)r * NDIM + tid] = lo;
        if (r + 1 < NN) H[(size_t)(r + 1) * NDIM + tid] = hi;
    }
}

// ---------------- attention scores -----------------------------------------
__global__ void ascore1_k(const float* __restrict__ att_s, const float* __restrict__ att_d) {
    int g = blockIdx.x * blockDim.x + threadIdx.x;
    int warp = g >> 5, lane = g & 31;
    if (warp >= NN * NH1) return;
    int n = warp >> 2, h = warp & 3;
    const float* hp = &g_h1[(size_t)n * D1 + h * C1C];
    float s = 0.f, d0 = 0.f;
#pragma unroll
    for (int c = lane; c < C1C; c += 32) {
        float v = hp[c];
        s  = fmaf(v, __ldg(&att_s[h * C1C + c]), s);
        d0 = fmaf(v, __ldg(&att_d[h * C1C + c]), d0);
    }
#pragma unroll
    for (int o = 16; o; o >>= 1) {
        s  += __shfl_down_sync(0xffffffffu, s, o);
        d0 += __shfl_down_sync(0xffffffffu, d0, o);
    }
    if (!lane) { g_asrc1[warp] = s; g_adst1[warp] = d0; }
}

__global__ void ascore2_k(const float* __restrict__ att_s, const float* __restrict__ att_d) {
    int g = blockIdx.x * blockDim.x + threadIdx.x;
    int warp = g >> 5, lane = g & 31;
    if (warp >= NN) return;
    const float* hp = &g_h2[(size_t)warp * D2];
    float s = 0.f, d0 = 0.f;
#pragma unroll
    for (int c = lane; c < D2; c += 32) {
        float v = hp[c];
        s  = fmaf(v, __ldg(&att_s[c]), s);
        d0 = fmaf(v, __ldg(&att_d[c]), d0);
    }
#pragma unroll
    for (int o = 16; o; o >>= 1) {
        s  += __shfl_down_sync(0xffffffffu, s, o);
        d0 += __shfl_down_sync(0xffffffffu, d0, o);
    }
    if (!lane) { g_asrc2[warp] = s; g_adst2[warp] = d0; }
}

// ---------------- fused softmax + aggregation (warp per dst node) ----------
// layer1: 4 heads, 256 channels. Pass1: per-head max. Pass2: recompute
// exp(lrelu(.)-mx) inline, accumulate denominator per-lane + weighted sum.
__global__ void agg1_k(const float* __restrict__ bias) {
    int g = blockIdx.x * blockDim.x + threadIdx.x;
    int d = g >> 5, lane = g & 31;
    if (d >= NN) return;
    int b = g_rowptr[d];
    int deg = g_rowptr[d + 1] - b;
    float ad0 = g_adst1[d * NH1 + 0], ad1 = g_adst1[d * NH1 + 1];
    float ad2 = g_adst1[d * NH1 + 2], ad3 = g_adst1[d * NH1 + 3];

    float mx0 = -1e30f, mx1 = -1e30f, mx2 = -1e30f, mx3 = -1e30f;
    for (int i = lane; i < deg; i += 32) {
        int s = g_col[b + i];
        float4 as = *reinterpret_cast<const float4*>(&g_asrc1[s * NH1]);
        mx0 = fmaxf(mx0, lrelu(as.x + ad0));
        mx1 = fmaxf(mx1, lrelu(as.y + ad1));
        mx2 = fmaxf(mx2, lrelu(as.z + ad2));
        mx3 = fmaxf(mx3, lrelu(as.w + ad3));
    }
#pragma unroll
    for (int o = 16; o; o >>= 1) {
        mx0 = fmaxf(mx0, __shfl_xor_sync(0xffffffffu, mx0, o));
        mx1 = fmaxf(mx1, __shfl_xor_sync(0xffffffffu, mx1, o));
        mx2 = fmaxf(mx2, __shfl_xor_sync(0xffffffffu, mx2, o));
        mx3 = fmaxf(mx3, __shfl_xor_sync(0xffffffffu, mx3, o));
    }

    int h0 = lane >> 4;                         // head of first float4 (0/1)
    float adA = h0 ? ad1 : ad0, adB = h0 ? ad3 : ad2;
    float mxA = h0 ? mx1 : mx0, mxB = h0 ? mx3 : mx2;
    float denA = 0.f, denB = 0.f;
    float4 acc0 = {0.f, 0.f, 0.f, 0.f};
    float4 acc1 = {0.f, 0.f, 0.f, 0.f};
    for (int i = 0; i < deg; i++) {
        int s = g_col[b + i];
        float aA = g_asrc1[s * NH1 + h0];
        float aB = g_asrc1[s * NH1 + 2 + h0];
        float eA = __expf(lrelu(aA + adA) - mxA);
        float eB = __expf(lrelu(aB + adB) - mxB);
        denA += eA; denB += eB;
        const float4* hp = reinterpret_cast<const float4*>(g_h1 + (size_t)s * D1);
        float4 v0 = hp[lane];
        float4 v1 = hp[lane + 32];
        acc0.x = fmaf(v0.x, eA, acc0.x); acc0.y = fmaf(v0.y, eA, acc0.y);
        acc0.z = fmaf(v0.z, eA, acc0.z); acc0.w = fmaf(v0.w, eA, acc0.w);
        acc1.x = fmaf(v1.x, eB, acc1.x); acc1.y = fmaf(v1.y, eB, acc1.y);
        acc1.z = fmaf(v1.z, eB, acc1.z); acc1.w = fmaf(v1.w, eB, acc1.w);
    }
    float inv0 = 1.f / (denA + 1e-16f);
    float inv1 = 1.f / (denB + 1e-16f);
    const float4* bp = reinterpret_cast<const float4*>(bias);
    float4 b0 = __ldg(&bp[lane]);
    float4 b1 = __ldg(&bp[lane + 32]);
    float4 o0, o1;
    o0.x = elu(acc0.x * inv0 + b0.x); o0.y = elu(acc0.y * inv0 + b0.y);
    o0.z = elu(acc0.z * inv0 + b0.z); o0.w = elu(acc0.w * inv0 + b0.w);
    o1.x = elu(acc1.x * inv1 + b1.x); o1.y = elu(acc1.y * inv1 + b1.y);
    o1.z = elu(acc1.z * inv1 + b1.z); o1.w = elu(acc1.w * inv1 + b1.w);
    float4* op = reinterpret_cast<float4*>(g_out1 + (size_t)d * D1);
    op[lane] = o0;
    op[lane + 32] = o1;
}

// layer2: 1 head, 128 channels
__global__ void agg2_k(const float* __restrict__ bias) {
    int g = blockIdx.x * blockDim.x + threadIdx.x;
    int d = g >> 5, lane = g & 31;
    if (d >= NN) return;
    int b = g_rowptr[d];
    int deg = g_rowptr[d + 1] - b;
    float ad = g_adst2[d];
    float mx = -1e30f;
    for (int i = lane; i < deg; i += 32) {
        int s = g_col[b + i];
        mx = fmaxf(mx, lrelu(g_asrc2[s] + ad));
    }
#pragma unroll
    for (int o = 16; o; o >>= 1) mx = fmaxf(mx, __shfl_xor_sync(0xffffffffu, mx, o));

    float den = 0.f;
    float4 acc = {0.f, 0.f, 0.f, 0.f};
    for (int i = 0; i < deg; i++) {
        int s = g_col[b + i];
        float e = __expf(lrelu(g_asrc2[s] + ad) - mx);
        den += e;
        const float4* hp = reinterpret_cast<const float4*>(g_h2 + (size_t)s * D2);
        float4 v = hp[lane];
        acc.x = fmaf(v.x, e, acc.x); acc.y = fmaf(v.y, e, acc.y);
        acc.z = fmaf(v.z, e, acc.z); acc.w = fmaf(v.w, e, acc.w);
    }
    float inv = 1.f / (den + 1e-16f);
    const float4* bp = reinterpret_cast<const float4*>(bias);
    float4 bb = __ldg(&bp[lane]);
    float4 o;
    o.x = elu(acc.x * inv + bb.x); o.y = elu(acc.y * inv + bb.y);
    o.z = elu(acc.z * inv + bb.z); o.w = elu(acc.w * inv + bb.w);
    reinterpret_cast<float4*>(g_out2 + (size_t)d * D2)[lane] = o;
}

// ---------------- pooling (batch is sorted -> segmented accumulation) ------
#define NPB 128
__global__ void pool_k(const int* __restrict__ batch) {
    int c = threadIdx.x;                         // 0..127 channel
    int n0 = blockIdx.x * NPB;
    int n1 = min(NN, n0 + NPB);
    if (n0 >= NN) return;
    int curg = batch[n0];
    float acc = 0.f, cnt = 0.f;
    for (int n = n0; n < n1; n++) {
        int gg = batch[n];
        if (gg != curg) {
            atomicAdd(&g_pool[curg * D2 + c], acc);
            if (c == 0) atomicAdd(&g_cnt[curg], cnt);
            acc = 0.f; cnt = 0.f; curg = gg;
        }
        acc += g_out2[(size_t)n * D2 + c];
        cnt += 1.f;
    }
    atomicAdd(&g_pool[curg * D2 + c], acc);
    if (c == 0) atomicAdd(&g_cnt[curg], cnt);
}

__global__ void final_k(const float* __restrict__ lin_w, const float* __restrict__ lin_b,
                        float* __restrict__ out) {
    int t = threadIdx.x;
    if (t >= NG * NCLS) return;
    int gph = t / NCLS, k = t - gph * NCLS;
    float inv = 1.f / fmaxf(g_cnt[gph], 1.f);
    float acc = 0.f;
    for (int c = 0; c < D2; c++)
        acc = fmaf(g_pool[gph * D2 + c] * inv, __ldg(&lin_w[c * NCLS + k]), acc);
    out[t] = acc + lin_b[k];
}

// ---------------- driver -----------------------------------------------------
extern "C" void kernel_launch(void* const* d_in, const int* in_sizes, int n_in,
                              void* d_out, int out_size) {
    const float* x        = (const float*)d_in[0];
    const int*   ei       = (const int*)d_in[1];
    const int*   batch    = (const int*)d_in[2];
    const float* W1       = (const float*)d_in[3];
    const float* att_src1 = (const float*)d_in[4];
    const float* att_dst1 = (const float*)d_in[5];
    const float* b1       = (const float*)d_in[6];
    const float* W2       = (const float*)d_in[7];
    const float* att_src2 = (const float*)d_in[8];
    const float* att_dst2 = (const float*)d_in[9];
    const float* b2       = (const float*)d_in[10];
    const float* lin_w    = (const float*)d_in[11];
    const float* lin_b    = (const float*)d_in[12];
    float* out = (float*)d_out;

    float* h1p;   cudaGetSymbolAddress((void**)&h1p, g_h1);
    float* out1p; cudaGetSymbolAddress((void**)&out1p, g_out1);
    float* h2p;   cudaGetSymbolAddress((void**)&h2p, g_h2);

    init_kernel<<<256, 256>>>();
    deg_k<<<(ET + 255) / 256, 256>>>(ei);
    scan_k<<<1, 1024>>>();
    scatter_k<<<(ET + 255) / 256, 256>>>(ei);

    // ---- layer 1 ----
    gemm_k<FIN, D1, 32><<<(NN + 31) / 32, D1>>>(x, W1, h1p);
    ascore1_k<<<(NN * NH1 * 32 + 255) / 256, 256>>>(att_src1, att_dst1);
    agg1_k<<<(NN * 32 + 255) / 256, 256>>>(b1);

    // ---- layer 2 ----
    gemm_k<D1, D2, 32><<<(NN + 31) / 32, D2>>>(out1p, W2, h2p);
    ascore2_k<<<(NN * 32 + 255) / 256, 256>>>(att_src2, att_dst2);
    agg2_k<<<(NN * 32 + 255) / 256, 256>>>(b2);

    // ---- pooling + head ----
    pool_k<<<(NN + NPB - 1) / NPB, D2>>>(batch);
    final_k<<<1, 256>>>(lin_w, lin_b, out);
}

// round 9
// speedup vs baseline: 2.4199x; 1.0387x over previous
#include <cuda_runtime.h>

#define NN 50000
#define EE 800000
#define ET 850000        // EE + NN self loops
#define FIN 128
#define D1 256           // H1*C1 = 4*64
#define C1C 64
#define NH1 4
#define D2 128
#define NG 32
#define NCLS 5
#define NEG_SLOPE 0.2f

// ---------------- scratch (static device globals) ---------------------------
__device__ float g_h1[(size_t)NN * D1];
__device__ float g_out1[(size_t)NN * D1];
__device__ float g_h2[(size_t)NN * D2];
__device__ float g_out2[(size_t)NN * D2];
__device__ float g_asrc1[NN * NH1], g_adst1[NN * NH1];
__device__ float g_asrc2[NN], g_adst2[NN];
__device__ float g_pool[NG * D2];
__device__ float g_cnt[NG];
// CSR by destination
__device__ int g_deg[NN];
__device__ int g_rowptr[NN + 1];
__device__ int g_cursor[NN];
__device__ int g_col[ET];

__device__ __forceinline__ float lrelu(float a) { return (a > 0.f) ? a : NEG_SLOPE * a; }
__device__ __forceinline__ float elu(float v)   { return (v > 0.f) ? v : expm1f(v); }

// ---------------- init ------------------------------------------------------
__global__ void init_kernel() {
    int i0 = blockIdx.x * blockDim.x + threadIdx.x;
    int stride = gridDim.x * blockDim.x;
    for (int i = i0; i < NN; i += stride) g_deg[i] = 0;
    for (int i = i0; i < NG * D2; i += stride) g_pool[i] = 0.f;
    if (i0 < NG) g_cnt[i0] = 0.f;
}

// ---------------- CSR build -------------------------------------------------
__global__ void deg_k(const int* __restrict__ ei) {
    int e = blockIdx.x * blockDim.x + threadIdx.x;
    if (e >= ET) return;
    int d = (e < EE) ? ei[EE + e] : (e - EE);
    atomicAdd(&g_deg[d], 1);
}

__global__ void scan_k() {
    const int T = 1024;
    const int CH = (NN + T - 1) / T;
    __shared__ int part[T];
    int t = threadIdx.x;
    int base = t * CH;
    int s = 0;
    for (int i = 0; i < CH; i++) {
        int idx = base + i;
        if (idx < NN) s += g_deg[idx];
    }
    part[t] = s;
    __syncthreads();
    for (int off = 1; off < T; off <<= 1) {
        int v = (t >= off) ? part[t - off] : 0;
        __syncthreads();
        part[t] += v;
        __syncthreads();
    }
    int run = part[t] - s;
    for (int i = 0; i < CH; i++) {
        int idx = base + i;
        if (idx < NN) {
            g_rowptr[idx] = run;
            g_cursor[idx] = run;
            run += g_deg[idx];
        }
    }
    if (t == 0) g_rowptr[NN] = ET;
}

__global__ void scatter_k(const int* __restrict__ ei) {
    int e = blockIdx.x * blockDim.x + threadIdx.x;
    if (e >= ET) return;
    int s, d;
    if (e < EE) { s = ei[e]; d = ei[EE + e]; }
    else        { s = e - EE; d = s; }
    int pos = atomicAdd(&g_cursor[d], 1);
    g_col[pos] = s;
}

// ---------------- GEMM (packed f32x2) + fused attention scores -------------
// H[r, tid] = sum_k X[r,k] * W[k, tid];  also
// asrc[r,h] = sum_c H[r,h*SPAN+c]*att_s[h,c], adst likewise.
template <int KDIM, int NDIM, int TM, int HEADS>
__global__ void gemm_att_k(const float* __restrict__ X, const float* __restrict__ W,
                           float* __restrict__ H,
                           const float* __restrict__ att_s, const float* __restrict__ att_d,
                           float* __restrict__ asrc, float* __restrict__ adst) {
    constexpr int STRIDE = TM + 4;                  // 36 floats = 144B
    constexpr int NWARP = NDIM / 32;
    __shared__ __align__(16) float xs[KDIM * STRIDE];
    __shared__ float part[NWARP * TM * 2];
    int row0 = blockIdx.x * TM;
    int tid = threadIdx.x;                          // NDIM threads
    for (int i = tid; i < TM * KDIM; i += NDIM) {
        int m = i / KDIM, k = i - m * KDIM;
        int r = row0 + m;
        xs[k * STRIDE + m] = (r < NN) ? X[(size_t)r * KDIM + k] : 0.f;
    }
    __syncthreads();

    unsigned long long acc[TM / 2];
#pragma unroll
    for (int p = 0; p < TM / 2; p++) acc[p] = 0ull;

    for (int k = 0; k < KDIM; k += 2) {
        float wa = W[(size_t)k * NDIM + tid];
        float wb = W[(size_t)(k + 1) * NDIM + tid];
        unsigned long long wpa, wpb;
        asm("mov.b64 %0, {%1, %1};" : "=l"(wpa) : "f"(wa));
        asm("mov.b64 %0, {%1, %1};" : "=l"(wpb) : "f"(wb));
        const ulonglong2* xa = reinterpret_cast<const ulonglong2*>(&xs[k * STRIDE]);
        const ulonglong2* xb = reinterpret_cast<const ulonglong2*>(&xs[(k + 1) * STRIDE]);
#pragma unroll
        for (int q = 0; q < TM / 4; q++) {
            ulonglong2 va = xa[q];
            asm("fma.rn.f32x2 %0, %1, %2, %0;" : "+l"(acc[2 * q])     : "l"(va.x), "l"(wpa));
            asm("fma.rn.f32x2 %0, %1, %2, %0;" : "+l"(acc[2 * q + 1]) : "l"(va.y), "l"(wpa));
        }
#pragma unroll
        for (int q = 0; q < TM / 4; q++) {
            ulonglong2 vb = xb[q];
            asm("fma.rn.f32x2 %0, %1, %2, %0;" : "+l"(acc[2 * q])     : "l"(vb.x), "l"(wpb));
            asm("fma.rn.f32x2 %0, %1, %2, %0;" : "+l"(acc[2 * q + 1]) : "l"(vb.y), "l"(wpb));
        }
    }

    int lane = tid & 31, w = tid >> 5;
    float as = __ldg(&att_s[tid]);
    float ad = __ldg(&att_d[tid]);
#pragma unroll
    for (int p = 0; p < TM / 2; p++) {
        float lo, hi;
        asm("mov.b64 {%0, %1}, %2;" : "=f"(lo), "=f"(hi) : "l"(acc[p]));
        int r = row0 + 2 * p;
        if (r < NN)     H[(size_t)r * NDIM + tid] = lo;
        if (r + 1 < NN) H[(size_t)(r + 1) * NDIM + tid] = hi;
        float s0 = lo * as, d0 = lo * ad, s1 = hi * as, d1 = hi * ad;
#pragma unroll
        for (int o = 16; o; o >>= 1) {
            s0 += __shfl_xor_sync(0xffffffffu, s0, o);
            d0 += __shfl_xor_sync(0xffffffffu, d0, o);
            s1 += __shfl_xor_sync(0xffffffffu, s1, o);
            d1 += __shfl_xor_sync(0xffffffffu, d1, o);
        }
        if (!lane) {
            part[w * (TM * 2) + (2 * p) * 2 + 0] = s0;
            part[w * (TM * 2) + (2 * p) * 2 + 1] = d0;
            part[w * (TM * 2) + (2 * p + 1) * 2 + 0] = s1;
            part[w * (TM * 2) + (2 * p + 1) * 2 + 1] = d1;
        }
    }
    __syncthreads();
    constexpr int WPH = NWARP / HEADS;              // warps per head
    if (tid < TM * HEADS * 2) {
        int m = tid % TM;
        int rest = tid / TM;
        int h = rest % HEADS;
        int v = rest / HEADS;
        float sum = 0.f;
#pragma unroll
        for (int q = 0; q < WPH; q++) sum += part[(h * WPH + q) * (TM * 2) + m * 2 + v];
        int r = row0 + m;
        if (r < NN) {
            if (v == 0) asrc[r * HEADS + h] = sum;
            else        adst[r * HEADS + h] = sum;
        }
    }
}

// ---------------- fused softmax + aggregation (warp per dst node) ----------
// layer1: 4 heads, 256 channels; depth-2 software pipeline on the gather.
__global__ void agg1_k(const float* __restrict__ bias) {
    int g = blockIdx.x * blockDim.x + threadIdx.x;
    int d = g >> 5, lane = g & 31;
    if (d >= NN) return;
    int b = g_rowptr[d];
    int deg = g_rowptr[d + 1] - b;
    float ad0 = g_adst1[d * NH1 + 0], ad1 = g_adst1[d * NH1 + 1];
    float ad2 = g_adst1[d * NH1 + 2], ad3 = g_adst1[d * NH1 + 3];

    float mx0 = -1e30f, mx1 = -1e30f, mx2 = -1e30f, mx3 = -1e30f;
    for (int i = lane; i < deg; i += 32) {
        int s = g_col[b + i];
        float4 a = *reinterpret_cast<const float4*>(&g_asrc1[s * NH1]);
        mx0 = fmaxf(mx0, lrelu(a.x + ad0));
        mx1 = fmaxf(mx1, lrelu(a.y + ad1));
        mx2 = fmaxf(mx2, lrelu(a.z + ad2));
        mx3 = fmaxf(mx3, lrelu(a.w + ad3));
    }
#pragma unroll
    for (int o = 16; o; o >>= 1) {
        mx0 = fmaxf(mx0, __shfl_xor_sync(0xffffffffu, mx0, o));
        mx1 = fmaxf(mx1, __shfl_xor_sync(0xffffffffu, mx1, o));
        mx2 = fmaxf(mx2, __shfl_xor_sync(0xffffffffu, mx2, o));
        mx3 = fmaxf(mx3, __shfl_xor_sync(0xffffffffu, mx3, o));
    }

    int h0 = lane >> 4;
    float adA = h0 ? ad1 : ad0, adB = h0 ? ad3 : ad2;
    float mxA = h0 ? mx1 : mx0, mxB = h0 ? mx3 : mx2;
    float denA = 0.f, denB = 0.f;
    float4 acc0 = {0.f, 0.f, 0.f, 0.f};
    float4 acc1 = {0.f, 0.f, 0.f, 0.f};

    // prologue: load edge 0
    int s0 = g_col[b];
    float aA = g_asrc1[s0 * NH1 + h0];
    float aB = g_asrc1[s0 * NH1 + 2 + h0];
    const float4* hp = reinterpret_cast<const float4*>(g_h1 + (size_t)s0 * D1);
    float4 v0 = hp[lane];
    float4 v1 = hp[lane + 32];
    for (int i = 0; i < deg; i++) {
        int j = min(i + 1, deg - 1);
        int sn = g_col[b + j];
        float aAn = g_asrc1[sn * NH1 + h0];
        float aBn = g_asrc1[sn * NH1 + 2 + h0];
        const float4* hpn = reinterpret_cast<const float4*>(g_h1 + (size_t)sn * D1);
        float4 v0n = hpn[lane];
        float4 v1n = hpn[lane + 32];
        float eA = __expf(lrelu(aA + adA) - mxA);
        float eB = __expf(lrelu(aB + adB) - mxB);
        denA += eA; denB += eB;
        acc0.x = fmaf(v0.x, eA, acc0.x); acc0.y = fmaf(v0.y, eA, acc0.y);
        acc0.z = fmaf(v0.z, eA, acc0.z); acc0.w = fmaf(v0.w, eA, acc0.w);
        acc1.x = fmaf(v1.x, eB, acc1.x); acc1.y = fmaf(v1.y, eB, acc1.y);
        acc1.z = fmaf(v1.z, eB, acc1.z); acc1.w = fmaf(v1.w, eB, acc1.w);
        aA = aAn; aB = aBn; v0 = v0n; v1 = v1n;
    }
    float inv0 = 1.f / (denA + 1e-16f);
    float inv1 = 1.f / (denB + 1e-16f);
    const float4* bp = reinterpret_cast<const float4*>(bias);
    float4 b0 = __ldg(&bp[lane]);
    float4 b1 = __ldg(&bp[lane + 32]);
    float4 o0, o1;
    o0.x = elu(acc0.x * inv0 + b0.x); o0.y = elu(acc0.y * inv0 + b0.y);
    o0.z = elu(acc0.z * inv0 + b0.z); o0.w = elu(acc0.w * inv0 + b0.w);
    o1.x = elu(acc1.x * inv1 + b1.x); o1.y = elu(acc1.y * inv1 + b1.y);
    o1.z = elu(acc1.z * inv1 + b1.z); o1.w = elu(acc1.w * inv1 + b1.w);
    float4* op = reinterpret_cast<float4*>(g_out1 + (size_t)d * D1);
    op[lane] = o0;
    op[lane + 32] = o1;
}

// layer2: 1 head, 128 channels
__global__ void agg2_k(const float* __restrict__ bias) {
    int g = blockIdx.x * blockDim.x + threadIdx.x;
    int d = g >> 5, lane = g & 31;
    if (d >= NN) return;
    int b = g_rowptr[d];
    int deg = g_rowptr[d + 1] - b;
    float ad = g_adst2[d];
    float mx = -1e30f;
    for (int i = lane; i < deg; i += 32) {
        int s = g_col[b + i];
        mx = fmaxf(mx, lrelu(g_asrc2[s] + ad));
    }
#pragma unroll
    for (int o = 16; o; o >>= 1) mx = fmaxf(mx, __shfl_xor_sync(0xffffffffu, mx, o));

    float den = 0.f;
    float4 acc = {0.f, 0.f, 0.f, 0.f};
    int s0 = g_col[b];
    float a = g_asrc2[s0];
    float4 v = reinterpret_cast<const float4*>(g_h2 + (size_t)s0 * D2)[lane];
    for (int i = 0; i < deg; i++) {
        int j = min(i + 1, deg - 1);
        int sn = g_col[b + j];
        float an = g_asrc2[sn];
        float4 vn = reinterpret_cast<const float4*>(g_h2 + (size_t)sn * D2)[lane];
        float e = __expf(lrelu(a + ad) - mx);
        den += e;
        acc.x = fmaf(v.x, e, acc.x); acc.y = fmaf(v.y, e, acc.y);
        acc.z = fmaf(v.z, e, acc.z); acc.w = fmaf(v.w, e, acc.w);
        a = an; v = vn;
    }
    float inv = 1.f / (den + 1e-16f);
    const float4* bp = reinterpret_cast<const float4*>(bias);
    float4 bb = __ldg(&bp[lane]);
    float4 o;
    o.x = elu(acc.x * inv + bb.x); o.y = elu(acc.y * inv + bb.y);
    o.z = elu(acc.z * inv + bb.z); o.w = elu(acc.w * inv + bb.w);
    reinterpret_cast<float4*>(g_out2 + (size_t)d * D2)[lane] = o;
}

// ---------------- pooling (batch sorted -> segmented accumulation) ---------
#define NPB 128
__global__ void pool_k(const int* __restrict__ batch) {
    int c = threadIdx.x;
    int n0 = blockIdx.x * NPB;
    int n1 = min(NN, n0 + NPB);
    if (n0 >= NN) return;
    int curg = batch[n0];
    float acc = 0.f, cnt = 0.f;
    for (int n = n0; n < n1; n++) {
        int gg = batch[n];
        if (gg != curg) {
            atomicAdd(&g_pool[curg * D2 + c], acc);
            if (c == 0) atomicAdd(&g_cnt[curg], cnt);
            acc = 0.f; cnt = 0.f; curg = gg;
        }
        acc += g_out2[(size_t)n * D2 + c];
        cnt += 1.f;
    }
    atomicAdd(&g_pool[curg * D2 + c], acc);
    if (c == 0) atomicAdd(&g_cnt[curg], cnt);
}

__global__ void final_k(const float* __restrict__ lin_w, const float* __restrict__ lin_b,
                        float* __restrict__ out) {
    int t = threadIdx.x;
    if (t >= NG * NCLS) return;
    int gph = t / NCLS, k = t - gph * NCLS;
    float inv = 1.f / fmaxf(g_cnt[gph], 1.f);
    float acc = 0.f;
    for (int c = 0; c < D2; c++)
        acc = fmaf(g_pool[gph * D2 + c] * inv, __ldg(&lin_w[c * NCLS + k]), acc);
    out[t] = acc + lin_b[k];
}

// ---------------- driver -----------------------------------------------------
extern "C" void kernel_launch(void* const* d_in, const int* in_sizes, int n_in,
                              void* d_out, int out_size) {
    const float* x        = (const float*)d_in[0];
    const int*   ei       = (const int*)d_in[1];
    const int*   batch    = (const int*)d_in[2];
    const float* W1       = (const float*)d_in[3];
    const float* att_src1 = (const float*)d_in[4];
    const float* att_dst1 = (const float*)d_in[5];
    const float* b1       = (const float*)d_in[6];
    const float* W2       = (const float*)d_in[7];
    const float* att_src2 = (const float*)d_in[8];
    const float* att_dst2 = (const float*)d_in[9];
    const float* b2       = (const float*)d_in[10];
    const float* lin_w    = (const float*)d_in[11];
    const float* lin_b    = (const float*)d_in[12];
    float* out = (float*)d_out;

    static cudaStream_t s1 = 0;
    static cudaEvent_t evRoot = 0, evCsr = 0;
    static int inited = 0;
    if (!inited) {   // first call is the (non-captured) correctness run
        cudaStreamCreateWithFlags(&s1, cudaStreamNonBlocking);
        cudaEventCreateWithFlags(&evRoot, cudaEventDisableTiming);
        cudaEventCreateWithFlags(&evCsr, cudaEventDisableTiming);
        inited = 1;
    }

    float* h1p;    cudaGetSymbolAddress((void**)&h1p, g_h1);
    float* out1p;  cudaGetSymbolAddress((void**)&out1p, g_out1);
    float* h2p;    cudaGetSymbolAddress((void**)&h2p, g_h2);
    float* as1p;   cudaGetSymbolAddress((void**)&as1p, g_asrc1);
    float* ad1p;   cudaGetSymbolAddress((void**)&ad1p, g_adst1);
    float* as2p;   cudaGetSymbolAddress((void**)&as2p, g_asrc2);
    float* ad2p;   cudaGetSymbolAddress((void**)&ad2p, g_adst2);

    // fork: CSR build on s1, GEMM path on stream 0
    cudaEventRecord(evRoot, 0);
    cudaStreamWaitEvent(s1, evRoot, 0);
    init_kernel<<<256, 256, 0, s1>>>();
    deg_k<<<(ET + 255) / 256, 256, 0, s1>>>(ei);
    scan_k<<<1, 1024, 0, s1>>>();
    scatter_k<<<(ET + 255) / 256, 256, 0, s1>>>(ei);
    cudaEventRecord(evCsr, s1);

    gemm_att_k<FIN, D1, 32, NH1><<<(NN + 31) / 32, D1>>>(
        x, W1, h1p, att_src1, att_dst1, as1p, ad1p);

    // join: agg needs CSR
    cudaStreamWaitEvent(0, evCsr, 0);
    agg1_k<<<(NN * 32 + 255) / 256, 256>>>(b1);

    gemm_att_k<D1, D2, 32, 1><<<(NN + 31) / 32, D2>>>(
        out1p, W2, h2p, att_src2, att_dst2, as2p, ad2p);
    agg2_k<<<(NN * 32 + 255) / 256, 256>>>(b2);

    pool_k<<<(NN + NPB - 1) / NPB, D2>>>(batch);
    final_k<<<1, 256>>>(lin_w, lin_b, out);
}